// round 3
// baseline (speedup 1.0000x reference)
#include <cuda_runtime.h>

typedef unsigned long long ULL;

__device__ __forceinline__ void ffma2(ULL &d, ULL a, ULL b) {
    asm("fma.rn.f32x2 %0, %1, %2, %0;" : "+l"(d) : "l"(a), "l"(b));
}
__device__ __forceinline__ float2 unpack2(ULL v) {
    float2 f; asm("mov.b64 {%0,%1}, %2;" : "=f"(f.x), "=f"(f.y) : "l"(v)); return f;
}
__device__ __forceinline__ ULL pack2(float lo, float hi) {
    ULL r; asm("mov.b64 %0, {%1,%2};" : "=l"(r) : "f"(lo), "f"(hi)); return r;
}
__device__ __forceinline__ ULL dup2(float a) {
    ULL r; asm("mov.b64 %0, {%1,%1};" : "=l"(r) : "f"(a)); return r;
}

__device__ __forceinline__ float sigf(float x)  { return __fdividef(1.f, 1.f + __expf(-x)); }
__device__ __forceinline__ float tanhf2(float x){ return 2.f * sigf(2.f * x) - 1.f; }

constexpr int B = 512, T = 512;
constexpr long BT = (long)B * T;
constexpr int RC = 4;

__device__ __align__(16) float g_h0T[128 * BT];
__device__ __align__(16) float g_xp1[BT * 512];
__device__ __align__(16) ULL   g_Btd[128 * 512];
__device__ float g_pooled[B * 128];

__device__ __forceinline__ float quad_reduce(float p0, float p1, float p2, float p3, int q)
{
    const bool hi = (q & 2) != 0;
    float s0 = hi ? p0 : p2;
    float s1 = hi ? p1 : p3;
    float r0 = __shfl_xor_sync(0xffffffffu, s0, 2);
    float r1 = __shfl_xor_sync(0xffffffffu, s1, 2);
    float t0 = (hi ? p2 : p0) + r0;
    float t1 = (hi ? p3 : p1) + r1;
    const bool od = (q & 1) != 0;
    float s  = od ? t0 : t1;
    float r  = __shfl_xor_sync(0xffffffffu, s, 1);
    return (od ? t1 : t0) + r;
}

#define DOT_BODY                                                                                     \
    const ulonglong2* h4 = (const ulonglong2*)(h_s[p] + j * 64 + q * 16);                            \
    ulonglong2 hA = h4[0], hB = h4[1], hC = h4[2], hD = h4[3];                                       \
    ULL a0 = 0, a1 = 0, a2 = 0, a3 = 0;                                                             \
    ffma2(a0, w2[0][0], hA.x); ffma2(a1, w2[1][0], hA.x); ffma2(a2, w2[2][0], hA.x); ffma2(a3, w2[3][0], hA.x); \
    ffma2(a0, w2[0][1], hA.y); ffma2(a1, w2[1][1], hA.y); ffma2(a2, w2[2][1], hA.y); ffma2(a3, w2[3][1], hA.y); \
    ffma2(a0, w2[0][2], hB.x); ffma2(a1, w2[1][2], hB.x); ffma2(a2, w2[2][2], hB.x); ffma2(a3, w2[3][2], hB.x); \
    ffma2(a0, w2[0][3], hB.y); ffma2(a1, w2[1][3], hB.y); ffma2(a2, w2[2][3], hB.y); ffma2(a3, w2[3][3], hB.y); \
    ffma2(a0, w2[0][4], hC.x); ffma2(a1, w2[1][4], hC.x); ffma2(a2, w2[2][4], hC.x); ffma2(a3, w2[3][4], hC.x); \
    ffma2(a0, w2[0][5], hC.y); ffma2(a1, w2[1][5], hC.y); ffma2(a2, w2[2][5], hC.y); ffma2(a3, w2[3][5], hC.y); \
    ffma2(a0, w2[0][6], hD.x); ffma2(a1, w2[1][6], hD.x); ffma2(a2, w2[2][6], hD.x); ffma2(a3, w2[3][6], hD.x); \
    ffma2(a0, w2[0][7], hD.y); ffma2(a1, w2[1][7], hD.y); ffma2(a2, w2[2][7], hD.y); ffma2(a3, w2[3][7], hD.y); \
    const float2 f0 = unpack2(a0), f1 = unpack2(a1), f2 = unpack2(a2), f3 = unpack2(a3);             \
    float pre = quad_reduce(f0.x + f0.y, f1.x + f1.y, f2.x + f2.y, f3.x + f3.y, q);

__global__ __launch_bounds__(256, 2) void lstm_l0(
    const float* __restrict__ x,
    const float* __restrict__ Wih_f, const float* __restrict__ Whh_f, const float* __restrict__ b_f,
    const float* __restrict__ Wih_b, const float* __restrict__ Whh_b, const float* __restrict__ b_b)
{
    const int dir = blockIdx.y;
    const int b0  = blockIdx.x * RC;
    const int tid = threadIdx.x;
    const int u   = tid >> 2;
    const int q   = tid & 3;
    const int myrow = q * 64 + u;

    const float* Wih = dir ? Wih_b : Wih_f;
    const float* Whh = dir ? Whh_b : Whh_f;
    const float* bb  = dir ? b_b   : b_f;

    __shared__ __align__(16) float h_s[2][RC * 64];
    __shared__ __align__(16) float4 x_s[2][RC];
    __shared__ __align__(16) float hist[RC][64][36];

    ULL w2[4][8];
    #pragma unroll
    for (int g = 0; g < 4; g++) {
        const ULL* wp = (const ULL*)(Whh + (g * 64 + u) * 64 + q * 16);
        #pragma unroll
        for (int i = 0; i < 8; i++) w2[g][i] = wp[i];
    }
    const float4 wih = *(const float4*)(Wih + myrow * 4);
    const float bias = bb[myrow];

    const int lane = tid & 31;
    const int qb   = lane & ~3;

    for (int i = tid; i < RC * 64; i += 256) h_s[0][i] = 0.f;
    if (tid < RC) {
        const int t0 = dir ? (T - 1) : 0;
        x_s[0][tid] = *(const float4*)(x + ((long)(b0 + tid) * T + t0) * 4);
    }
    __syncthreads();

    float c[RC] = {0.f, 0.f, 0.f, 0.f};
    int p = 0;

    for (int s = 0; s < T; s++) {
        const int t = dir ? (T - 1 - s) : s;
        if (tid < RC) {
            const int sn = (s + 1 < T) ? s + 1 : s;
            const int tn = dir ? (T - 1 - sn) : sn;
            x_s[p ^ 1][tid] = *(const float4*)(x + ((long)(b0 + tid) * T + tn) * 4);
        }

        #pragma unroll
        for (int j = 0; j < RC; j++) {
            DOT_BODY
            const float4 xv = x_s[p][j];
            pre += bias + wih.x * xv.x + wih.y * xv.y + wih.z * xv.z + wih.w * xv.w;
            const float act = (q == 2) ? tanhf2(pre) : sigf(pre);
            const float iv = __shfl_sync(0xffffffffu, act, qb + 0);
            const float fv = __shfl_sync(0xffffffffu, act, qb + 1);
            const float gv = __shfl_sync(0xffffffffu, act, qb + 2);
            const float ov = __shfl_sync(0xffffffffu, act, qb + 3);
            c[j] = fmaf(fv, c[j], iv * gv);
            const float h = ov * tanhf2(c[j]);
            if (q == 0) {
                h_s[p ^ 1][j * 64 + u] = h;
                hist[j][u][t & 31] = h;
            }
        }
        p ^= 1;
        __syncthreads();

        if ((s & 31) == 31) {
            const int tbase = t & ~31;
            #pragma unroll
            for (int w = 0; w < 8; w++) {
                const int e   = tid + w * 256;
                const int tw4 = e & 7;
                const int ju  = e >> 3;
                const int j   = ju >> 6, uu = ju & 63;
                const float4 v = *(const float4*)(&hist[j][uu][tw4 * 4]);
                *(float4*)(g_h0T + (long)(dir * 64 + uu) * BT + (long)(b0 + j) * T + tbase + tw4 * 4) = v;
            }
            __syncthreads();
        }
    }
}

__global__ void prep_btd(const float* __restrict__ Wf, const float* __restrict__ Wb)
{
    const int idx = blockIdx.x * 512 + threadIdx.x;
    const int k = idx >> 9, n = idx & 511;
    const float* W = (n & 256) ? Wb : Wf;
    g_Btd[idx] = dup2(W[(n & 255) * 128 + k]);
}

constexpr int AP = 132;
constexpr int SMEM_GEMM = 64 * AP * 4 + 64 * 128 * 8;   // 99328

__global__ __launch_bounds__(256, 2) void gemm_xp1(
    const float* __restrict__ bias_f, const float* __restrict__ bias_b)
{
    extern __shared__ char smraw[];
    float* As  = (float*)smraw;
    ULL*   Bsd = (ULL*)(smraw + 64 * AP * 4);
    const int tid = threadIdx.x;
    const long m0 = (long)blockIdx.x * 128;
    const int  n0 = blockIdx.y * 128;

    const int tx = tid & 15;
    const int ty = tid >> 4;

    ULL acc[4][8];
    #pragma unroll
    for (int i = 0; i < 4; i++)
        #pragma unroll
        for (int j = 0; j < 8; j++) acc[i][j] = 0;

    for (int kc = 0; kc < 2; kc++) {
        const int k0 = kc * 64;
        __syncthreads();
        #pragma unroll
        for (int i = 0; i < 8; i++) {
            const int e = tid + i * 256;
            const int k = e >> 5, m4 = (e & 31) * 4;
            *(float4*)(As + k * AP + m4) = *(const float4*)(g_h0T + (long)(k0 + k) * BT + m0 + m4);
        }
        // Bsd: 64 k-rows x 64 ULL = 4096 ULL = 2048 ulonglong2; 256 thr x 8
        #pragma unroll
        for (int i = 0; i < 8; i++) {
            const int e = tid + i * 256;
            const int k = e >> 5, w = e & 31;
            *(ulonglong2*)(Bsd + k * 128 + w * 2 + ((w >= 0) ? 0 : 0)) =
                *(const ulonglong2*)(g_Btd + (long)(k0 + k) * 512 + n0 + w * 2);
        }
        // second half of each k-row (ULLs 64..127)
        #pragma unroll
        for (int i = 0; i < 8; i++) {
            const int e = tid + i * 256;
            const int k = e >> 5, w = e & 31;
            *(ulonglong2*)(Bsd + k * 128 + 64 + w * 2) =
                *(const ulonglong2*)(g_Btd + (long)(k0 + k) * 512 + n0 + 64 + w * 2);
        }
        __syncthreads();

        #pragma unroll 4
        for (int k = 0; k < 64; k++) {
            const ulonglong2* ap = (const ulonglong2*)(As + k * AP + ty * 8);
            const ulonglong2 aA = ap[0], aB = ap[1];
            const ulonglong2* bq = (const ulonglong2*)(Bsd + k * 128 + tx * 8);
            const ulonglong2 b01 = bq[0], b23 = bq[1], b45 = bq[2], b67 = bq[3];
            ffma2(acc[0][0], aA.x, b01.x); ffma2(acc[1][0], aA.y, b01.x);
            ffma2(acc[2][0], aB.x, b01.x); ffma2(acc[3][0], aB.y, b01.x);
            ffma2(acc[0][1], aA.x, b01.y); ffma2(acc[1][1], aA.y, b01.y);
            ffma2(acc[2][1], aB.x, b01.y); ffma2(acc[3][1], aB.y, b01.y);
            ffma2(acc[0][2], aA.x, b23.x); ffma2(acc[1][2], aA.y, b23.x);
            ffma2(acc[2][2], aB.x, b23.x); ffma2(acc[3][2], aB.y, b23.x);
            ffma2(acc[0][3], aA.x, b23.y); ffma2(acc[1][3], aA.y, b23.y);
            ffma2(acc[2][3], aB.x, b23.y); ffma2(acc[3][3], aB.y, b23.y);
            ffma2(acc[0][4], aA.x, b45.x); ffma2(acc[1][4], aA.y, b45.x);
            ffma2(acc[2][4], aB.x, b45.x); ffma2(acc[3][4], aB.y, b45.x);
            ffma2(acc[0][5], aA.x, b45.y); ffma2(acc[1][5], aA.y, b45.y);
            ffma2(acc[2][5], aB.x, b45.y); ffma2(acc[3][5], aB.y, b45.y);
            ffma2(acc[0][6], aA.x, b67.x); ffma2(acc[1][6], aA.y, b67.x);
            ffma2(acc[2][6], aB.x, b67.x); ffma2(acc[3][6], aB.y, b67.x);
            ffma2(acc[0][7], aA.x, b67.y); ffma2(acc[1][7], aA.y, b67.y);
            ffma2(acc[2][7], aB.x, b67.y); ffma2(acc[3][7], aB.y, b67.y);
        }
    }

    const float* bp = (n0 & 256) ? bias_b : bias_f;
    float bj[8];
    #pragma unroll
    for (int j = 0; j < 8; j++) bj[j] = bp[((n0 & 255) + tx * 8 + j) & 255];
    #pragma unroll
    for (int i = 0; i < 4; i++) {
        const long m = m0 + ty * 8 + i * 2;
        float4 lo0, lo1, hi0, hi1;
        float2 v;
        v = unpack2(acc[i][0]); lo0.x = v.x + bj[0]; hi0.x = v.y + bj[0];
        v = unpack2(acc[i][1]); lo0.y = v.x + bj[1]; hi0.y = v.y + bj[1];
        v = unpack2(acc[i][2]); lo0.z = v.x + bj[2]; hi0.z = v.y + bj[2];
        v = unpack2(acc[i][3]); lo0.w = v.x + bj[3]; hi0.w = v.y + bj[3];
        v = unpack2(acc[i][4]); lo1.x = v.x + bj[4]; hi1.x = v.y + bj[4];
        v = unpack2(acc[i][5]); lo1.y = v.x + bj[5]; hi1.y = v.y + bj[5];
        v = unpack2(acc[i][6]); lo1.z = v.x + bj[6]; hi1.z = v.y + bj[6];
        v = unpack2(acc[i][7]); lo1.w = v.x + bj[7]; hi1.w = v.y + bj[7];
        float* r0 = g_xp1 + m * 512 + n0 + tx * 8;
        float* r1 = r0 + 512;
        *(float4*)(r0)     = lo0;
        *(float4*)(r0 + 4) = lo1;
        *(float4*)(r1)     = hi0;
        *(float4*)(r1 + 4) = hi1;
    }
}

__global__ __launch_bounds__(256, 2) void lstm_l1(
    const float* __restrict__ Whh_f, const float* __restrict__ Whh_b)
{
    const int dir = blockIdx.y;
    const int b0  = blockIdx.x * RC;
    const int tid = threadIdx.x;
    const int u   = tid >> 2;
    const int q   = tid & 3;
    const int myrow = q * 64 + u;
    const float* Whh = dir ? Whh_b : Whh_f;

    __shared__ __align__(16) float h_s[2][RC * 64];

    ULL w2[4][8];
    #pragma unroll
    for (int g = 0; g < 4; g++) {
        const ULL* wp = (const ULL*)(Whh + (g * 64 + u) * 64 + q * 16);
        #pragma unroll
        for (int i = 0; i < 8; i++) w2[g][i] = wp[i];
    }
    const int lane = tid & 31;
    const int qb   = lane & ~3;
    const int col  = dir * 256 + myrow;

    for (int i = tid; i < RC * 64; i += 256) h_s[0][i] = 0.f;

    float c[RC]    = {0.f, 0.f, 0.f, 0.f};
    float hsum[RC] = {0.f, 0.f, 0.f, 0.f};
    float xp_cur[RC];
    {
        const int t0 = dir ? (T - 1) : 0;
        #pragma unroll
        for (int j = 0; j < RC; j++)
            xp_cur[j] = __ldg(g_xp1 + ((long)(b0 + j) * T + t0) * 512 + col);
    }
    __syncthreads();

    int p = 0;
    for (int s = 0; s < T; s++) {
        const int sn = (s + 1 < T) ? s + 1 : s;
        const int tn = dir ? (T - 1 - sn) : sn;
        float xp_nxt[RC];
        #pragma unroll
        for (int j = 0; j < RC; j++)
            xp_nxt[j] = __ldg(g_xp1 + ((long)(b0 + j) * T + tn) * 512 + col);

        #pragma unroll
        for (int j = 0; j < RC; j++) {
            DOT_BODY
            pre += xp_cur[j];
            const float act = (q == 2) ? tanhf2(pre) : sigf(pre);
            const float iv = __shfl_sync(0xffffffffu, act, qb + 0);
            const float fv = __shfl_sync(0xffffffffu, act, qb + 1);
            const float gv = __shfl_sync(0xffffffffu, act, qb + 2);
            const float ov = __shfl_sync(0xffffffffu, act, qb + 3);
            c[j] = fmaf(fv, c[j], iv * gv);
            const float h = ov * tanhf2(c[j]);
            hsum[j] += h;
            if (q == 0) h_s[p ^ 1][j * 64 + u] = h;
        }
        #pragma unroll
        for (int j = 0; j < RC; j++) xp_cur[j] = xp_nxt[j];
        p ^= 1;
        __syncthreads();
    }

    if (q == 0) {
        #pragma unroll
        for (int j = 0; j < RC; j++)
            g_pooled[(b0 + j) * 128 + dir * 64 + u] = hsum[j];
    }
}

__global__ void fc_kernel(const float* __restrict__ fcw, const float* __restrict__ fcb,
                          float* __restrict__ out)
{
    const int gw   = (blockIdx.x * blockDim.x + threadIdx.x) >> 5;
    const int lane = threadIdx.x & 31;
    if (gw >= B) return;
    float sum = 0.f;
    #pragma unroll
    for (int qq = 0; qq < 4; qq++)
        sum += g_pooled[gw * 128 + qq * 32 + lane] * fcw[qq * 32 + lane];
    #pragma unroll
    for (int o = 16; o; o >>= 1) sum += __shfl_xor_sync(0xffffffffu, sum, o);
    if (lane == 0) out[gw] = sum * (1.f / 512.f) + fcb[0];
}

extern "C" void kernel_launch(void* const* d_in, const int* in_sizes, int n_in,
                              void* d_out, int out_size)
{
    const float* x     = (const float*)d_in[0];
    const float* Wih0f = (const float*)d_in[1];
    const float* Whh0f = (const float*)d_in[2];
    const float* b0f   = (const float*)d_in[3];
    const float* Wih0b = (const float*)d_in[4];
    const float* Whh0b = (const float*)d_in[5];
    const float* b0b   = (const float*)d_in[6];
    const float* Wih1f = (const float*)d_in[7];
    const float* Whh1f = (const float*)d_in[8];
    const float* b1f   = (const float*)d_in[9];
    const float* Wih1b = (const float*)d_in[10];
    const float* Whh1b = (const float*)d_in[11];
    const float* b1b   = (const float*)d_in[12];
    const float* fcw   = (const float*)d_in[13];
    const float* fcb   = (const float*)d_in[14];

    prep_btd<<<128, 512>>>(Wih1f, Wih1b);
    lstm_l0<<<dim3(B / RC, 2), 256>>>(x, Wih0f, Whh0f, b0f, Wih0b, Whh0b, b0b);
    cudaFuncSetAttribute(gemm_xp1, cudaFuncAttributeMaxDynamicSharedMemorySize, SMEM_GEMM);
    gemm_xp1<<<dim3(2048, 4), 256, SMEM_GEMM>>>(b1f, b1b);
    lstm_l1<<<dim3(B / RC, 2), 256>>>(Whh1f, Whh1b);
    fc_kernel<<<32, 512>>>(fcw, fcb, (float*)d_out);
}

// round 4
// speedup vs baseline: 1.0379x; 1.0379x over previous
#include <cuda_runtime.h>

typedef unsigned long long ULL;

// ---------- packed fp32x2 helpers ----------
__device__ __forceinline__ void ffma2(ULL &d, ULL a, ULL b) {
    asm("fma.rn.f32x2 %0, %1, %2, %0;" : "+l"(d) : "l"(a), "l"(b));
}
__device__ __forceinline__ float2 unpack2(ULL v) {
    float2 f; asm("mov.b64 {%0,%1}, %2;" : "=f"(f.x), "=f"(f.y) : "l"(v)); return f;
}
__device__ __forceinline__ ULL dup2(float a) {
    ULL r; asm("mov.b64 %0, {%1,%1};" : "=l"(r) : "f"(a)); return r;
}

// ---------- activations ----------
__device__ __forceinline__ float sigf(float x)  { return __fdividef(1.f, 1.f + __expf(-x)); }
__device__ __forceinline__ float tanhf2(float x){ return 2.f * sigf(2.f * x) - 1.f; }

// ---------- constants ----------
constexpr int B = 512, T = 512;
constexpr long BT = (long)B * T;
constexpr int RC = 4;

// ---------- scratch ----------
__device__ __align__(16) float g_h0T[128 * BT];   // layer-0 out, feature-major [k][b*T+t]
__device__ __align__(16) float g_xp1[BT * 512];   // layer-1 preacts [b*T+t][n]
__device__ __align__(16) ULL   g_Btd[128 * 512];  // Wih_l1^T, values duplicated (b,b)
__device__ float g_pooled[B * 128];

// =======================================================================
// Layer-0 biLSTM. grid (128, 2), block 256, 2 CTAs/SM.
// Round-2 dot: thread owns gate row g*64+u (full 64-k weights in 32 ULL regs),
// computes it for 4 batch rows; broadcast LDS of h; 4-shfl gate exchange.
// h0 written TRANSPOSED via 32-step smem history tiles (coalesced flush).
// =======================================================================
__global__ __launch_bounds__(256, 2) void lstm_l0(
    const float* __restrict__ x,
    const float* __restrict__ Wih_f, const float* __restrict__ Whh_f, const float* __restrict__ b_f,
    const float* __restrict__ Wih_b, const float* __restrict__ Whh_b, const float* __restrict__ b_b)
{
    const int dir = blockIdx.y;
    const int b0  = blockIdx.x * RC;
    const int tid = threadIdx.x;
    const int u   = tid >> 2;
    const int g   = tid & 3;
    const int row = g * 64 + u;

    const float* Wih = dir ? Wih_b : Wih_f;
    const float* Whh = dir ? Whh_b : Whh_f;
    const float* bb  = dir ? b_b   : b_f;

    __shared__ __align__(16) float h_s[2][RC * 64];
    __shared__ __align__(16) float4 x_s[2][RC];
    __shared__ __align__(16) float hist[RC][64][36];

    ULL w2[32];
    {
        const ULL* wp = (const ULL*)(Whh + row * 64);
        #pragma unroll
        for (int i = 0; i < 32; i++) w2[i] = wp[i];
    }
    const float4 wih = *(const float4*)(Wih + row * 4);
    const float bias = bb[row];

    const int lane = tid & 31;
    const int qb   = lane & ~3;

    for (int i = tid; i < RC * 64; i += 256) h_s[0][i] = 0.f;
    if (tid < RC) {
        const int t0 = dir ? (T - 1) : 0;
        x_s[0][tid] = *(const float4*)(x + ((long)(b0 + tid) * T + t0) * 4);
    }
    __syncthreads();

    float c[RC] = {0.f, 0.f, 0.f, 0.f};
    int p = 0;

    for (int s = 0; s < T; s++) {
        const int t = dir ? (T - 1 - s) : s;
        if (tid < RC) {
            const int sn = (s + 1 < T) ? s + 1 : s;
            const int tn = dir ? (T - 1 - sn) : sn;
            x_s[p ^ 1][tid] = *(const float4*)(x + ((long)(b0 + tid) * T + tn) * 4);
        }

        float pre[RC];
        #pragma unroll
        for (int j = 0; j < RC; j++) {
            ULL a0 = 0, a1 = 0;
            const ulonglong2* h4 = (const ulonglong2*)(h_s[p] + j * 64);
            #pragma unroll
            for (int k = 0; k < 16; k++) {
                ulonglong2 hv = h4[k];
                ffma2(a0, w2[2 * k],     hv.x);
                ffma2(a1, w2[2 * k + 1], hv.y);
            }
            const float2 f0 = unpack2(a0), f1 = unpack2(a1);
            const float4 xv = x_s[p][j];
            pre[j] = f0.x + f0.y + f1.x + f1.y + bias
                   + wih.x * xv.x + wih.y * xv.y + wih.z * xv.z + wih.w * xv.w;
        }

        #pragma unroll
        for (int j = 0; j < RC; j++) {
            const float act = (g == 2) ? tanhf2(pre[j]) : sigf(pre[j]);
            const float iv = __shfl_sync(0xffffffffu, act, qb + 0);
            const float fv = __shfl_sync(0xffffffffu, act, qb + 1);
            const float gv = __shfl_sync(0xffffffffu, act, qb + 2);
            const float ov = __shfl_sync(0xffffffffu, act, qb + 3);
            c[j] = fmaf(fv, c[j], iv * gv);
            const float h = ov * tanhf2(c[j]);
            if (g == 0) {
                h_s[p ^ 1][j * 64 + u] = h;
                hist[j][u][t & 31] = h;
            }
        }
        p ^= 1;
        __syncthreads();

        if ((s & 31) == 31) {
            const int tbase = t & ~31;
            #pragma unroll
            for (int w = 0; w < 8; w++) {
                const int e   = tid + w * 256;
                const int tw4 = e & 7;
                const int ju  = e >> 3;
                const int j   = ju >> 6, uu = ju & 63;
                const float4 v = *(const float4*)(&hist[j][uu][tw4 * 4]);
                *(float4*)(g_h0T + (long)(dir * 64 + uu) * BT + (long)(b0 + j) * T + tbase + tw4 * 4) = v;
            }
            __syncthreads();
        }
    }
}

// =======================================================================
// Prep: g_Btd[k][n] = dup2(Wih_l1[n][k])  (n = dir*256 + gate_row)
// =======================================================================
__global__ void prep_btd(const float* __restrict__ Wf, const float* __restrict__ Wb)
{
    const int idx = blockIdx.x * 512 + threadIdx.x;   // 65536
    const int k = idx >> 9, n = idx & 511;
    const float* W = (n & 256) ? Wb : Wf;
    g_Btd[idx] = dup2(W[(n & 255) * 128 + k]);
}

// =======================================================================
// xp1 GEMM: [BT x 512] = h0T^T [BT x 128] @ W^T + bias.
// 128m x 128n tile, K split 2x64 (smem 97KB -> 2 CTAs/SM).
// A k-major (no transpose thanks to h0T), B pre-dup'd; FFMA2 packs M-pairs.
// grid (2048, 4), block 256.
// =======================================================================
constexpr int AP = 132;
constexpr int SMEM_GEMM = 64 * AP * 4 + 64 * 128 * 8;   // 99328 B

__global__ __launch_bounds__(256, 2) void gemm_xp1(
    const float* __restrict__ bias_f, const float* __restrict__ bias_b)
{
    extern __shared__ char smraw[];
    float* As  = (float*)smraw;                  // [64][AP]   k-major, m fastest
    ULL*   Bsd = (ULL*)(smraw + 64 * AP * 4);    // [64][128]  dup'd pairs
    const int tid = threadIdx.x;
    const long m0 = (long)blockIdx.x * 128;
    const int  n0 = blockIdx.y * 128;

    const int tx = tid & 15;        // n-octet
    const int ty = tid >> 4;        // m-octet

    ULL acc[4][8];
    #pragma unroll
    for (int i = 0; i < 4; i++)
        #pragma unroll
        for (int j = 0; j < 8; j++) acc[i][j] = 0;

    for (int kc = 0; kc < 2; kc++) {
        const int k0 = kc * 64;
        __syncthreads();
        // A slab: straight coalesced copy (already k-major)
        #pragma unroll
        for (int i = 0; i < 8; i++) {
            const int e = tid + i * 256;
            const int k = e >> 5, m4 = (e & 31) * 4;
            *(float4*)(As + k * AP + m4) = *(const float4*)(g_h0T + (long)(k0 + k) * BT + m0 + m4);
        }
        // B slab: 64 k-rows x 128 ULL, two passes of 2048 ulonglong2/2
        #pragma unroll
        for (int i = 0; i < 8; i++) {
            const int e = tid + i * 256;
            const int k = e >> 5, w = e & 31;
            *(ulonglong2*)(Bsd + k * 128 + w * 2) =
                *(const ulonglong2*)(g_Btd + (long)(k0 + k) * 512 + n0 + w * 2);
        }
        #pragma unroll
        for (int i = 0; i < 8; i++) {
            const int e = tid + i * 256;
            const int k = e >> 5, w = e & 31;
            *(ulonglong2*)(Bsd + k * 128 + 64 + w * 2) =
                *(const ulonglong2*)(g_Btd + (long)(k0 + k) * 512 + n0 + 64 + w * 2);
        }
        __syncthreads();

        #pragma unroll 4
        for (int k = 0; k < 64; k++) {
            const ulonglong2* ap = (const ulonglong2*)(As + k * AP + ty * 8);
            const ulonglong2 aA = ap[0], aB = ap[1];
            const ulonglong2* bq = (const ulonglong2*)(Bsd + k * 128 + tx * 8);
            const ulonglong2 b01 = bq[0], b23 = bq[1], b45 = bq[2], b67 = bq[3];
            ffma2(acc[0][0], aA.x, b01.x); ffma2(acc[1][0], aA.y, b01.x);
            ffma2(acc[2][0], aB.x, b01.x); ffma2(acc[3][0], aB.y, b01.x);
            ffma2(acc[0][1], aA.x, b01.y); ffma2(acc[1][1], aA.y, b01.y);
            ffma2(acc[2][1], aB.x, b01.y); ffma2(acc[3][1], aB.y, b01.y);
            ffma2(acc[0][2], aA.x, b23.x); ffma2(acc[1][2], aA.y, b23.x);
            ffma2(acc[2][2], aB.x, b23.x); ffma2(acc[3][2], aB.y, b23.x);
            ffma2(acc[0][3], aA.x, b23.y); ffma2(acc[1][3], aA.y, b23.y);
            ffma2(acc[2][3], aB.x, b23.y); ffma2(acc[3][3], aB.y, b23.y);
            ffma2(acc[0][4], aA.x, b45.x); ffma2(acc[1][4], aA.y, b45.x);
            ffma2(acc[2][4], aB.x, b45.x); ffma2(acc[3][4], aB.y, b45.x);
            ffma2(acc[0][5], aA.x, b45.y); ffma2(acc[1][5], aA.y, b45.y);
            ffma2(acc[2][5], aB.x, b45.y); ffma2(acc[3][5], aB.y, b45.y);
            ffma2(acc[0][6], aA.x, b67.x); ffma2(acc[1][6], aA.y, b67.x);
            ffma2(acc[2][6], aB.x, b67.x); ffma2(acc[3][6], aB.y, b67.x);
            ffma2(acc[0][7], aA.x, b67.y); ffma2(acc[1][7], aA.y, b67.y);
            ffma2(acc[2][7], aB.x, b67.y); ffma2(acc[3][7], aB.y, b67.y);
        }
    }

    const float* bp = (n0 & 256) ? bias_b : bias_f;
    float bj[8];
    #pragma unroll
    for (int j = 0; j < 8; j++) bj[j] = bp[((n0 & 255) + tx * 8 + j) & 255];
    #pragma unroll
    for (int i = 0; i < 4; i++) {
        const long m = m0 + ty * 8 + i * 2;
        float4 lo0, lo1, hi0, hi1;
        float2 v;
        v = unpack2(acc[i][0]); lo0.x = v.x + bj[0]; hi0.x = v.y + bj[0];
        v = unpack2(acc[i][1]); lo0.y = v.x + bj[1]; hi0.y = v.y + bj[1];
        v = unpack2(acc[i][2]); lo0.z = v.x + bj[2]; hi0.z = v.y + bj[2];
        v = unpack2(acc[i][3]); lo0.w = v.x + bj[3]; hi0.w = v.y + bj[3];
        v = unpack2(acc[i][4]); lo1.x = v.x + bj[4]; hi1.x = v.y + bj[4];
        v = unpack2(acc[i][5]); lo1.y = v.x + bj[5]; hi1.y = v.y + bj[5];
        v = unpack2(acc[i][6]); lo1.z = v.x + bj[6]; hi1.z = v.y + bj[6];
        v = unpack2(acc[i][7]); lo1.w = v.x + bj[7]; hi1.w = v.y + bj[7];
        float* r0 = g_xp1 + m * 512 + n0 + tx * 8;
        float* r1 = r0 + 512;
        *(float4*)(r0)     = lo0;
        *(float4*)(r0 + 4) = lo1;
        *(float4*)(r1)     = hi0;
        *(float4*)(r1 + 4) = hi1;
    }
}

// =======================================================================
// Layer-1 biLSTM: exact Round-2 version (best measured: 845 us).
// =======================================================================
__global__ __launch_bounds__(256, 2) void lstm_l1(
    const float* __restrict__ Whh_f, const float* __restrict__ Whh_b)
{
    const int dir = blockIdx.y;
    const int b0  = blockIdx.x * RC;
    const int tid = threadIdx.x;
    const int u   = tid >> 2;
    const int g   = tid & 3;
    const int row = g * 64 + u;
    const float* Whh = dir ? Whh_b : Whh_f;

    __shared__ __align__(16) float h_s[2][RC * 64];

    ULL w2[32];
    {
        const ULL* wp = (const ULL*)(Whh + row * 64);
        #pragma unroll
        for (int i = 0; i < 32; i++) w2[i] = wp[i];
    }
    const int lane = tid & 31;
    const int qb   = lane & ~3;
    const int col  = dir * 256 + row;

    const float* xp_base[RC];
    #pragma unroll
    for (int j = 0; j < RC; j++)
        xp_base[j] = g_xp1 + (long)(b0 + j) * T * 512 + col;

    for (int i = tid; i < RC * 64; i += 256) h_s[0][i] = 0.f;

    float c[RC]    = {0.f, 0.f, 0.f, 0.f};
    float hsum[RC] = {0.f, 0.f, 0.f, 0.f};
    float xp_cur[RC];
    {
        const int t0 = dir ? (T - 1) : 0;
        #pragma unroll
        for (int j = 0; j < RC; j++) xp_cur[j] = __ldg(xp_base[j] + (long)t0 * 512);
    }
    __syncthreads();

    int p = 0;
    for (int s = 0; s < T; s++) {
        const int sn = (s + 1 < T) ? s + 1 : s;
        const int tn = dir ? (T - 1 - sn) : sn;
        float xp_nxt[RC];
        #pragma unroll
        for (int j = 0; j < RC; j++) xp_nxt[j] = __ldg(xp_base[j] + (long)tn * 512);

        float pre[RC];
        #pragma unroll
        for (int j = 0; j < RC; j++) {
            ULL a0 = 0, a1 = 0;
            const ulonglong2* h4 = (const ulonglong2*)(h_s[p] + j * 64);
            #pragma unroll
            for (int k = 0; k < 16; k++) {
                ulonglong2 hv = h4[k];
                ffma2(a0, w2[2 * k],     hv.x);
                ffma2(a1, w2[2 * k + 1], hv.y);
            }
            const float2 f0 = unpack2(a0), f1 = unpack2(a1);
            pre[j] = f0.x + f0.y + f1.x + f1.y + xp_cur[j];
        }

        #pragma unroll
        for (int j = 0; j < RC; j++) {
            const float act = (g == 2) ? tanhf2(pre[j]) : sigf(pre[j]);
            const float iv = __shfl_sync(0xffffffffu, act, qb + 0);
            const float fv = __shfl_sync(0xffffffffu, act, qb + 1);
            const float gv = __shfl_sync(0xffffffffu, act, qb + 2);
            const float ov = __shfl_sync(0xffffffffu, act, qb + 3);
            c[j] = fmaf(fv, c[j], iv * gv);
            const float h = ov * tanhf2(c[j]);
            hsum[j] += h;
            if (g == 0) h_s[p ^ 1][j * 64 + u] = h;
        }
        #pragma unroll
        for (int j = 0; j < RC; j++) xp_cur[j] = xp_nxt[j];
        p ^= 1;
        __syncthreads();
    }

    if (g == 0) {
        #pragma unroll
        for (int j = 0; j < RC; j++)
            g_pooled[(b0 + j) * 128 + dir * 64 + u] = hsum[j];
    }
}

// =======================================================================
__global__ void fc_kernel(const float* __restrict__ fcw, const float* __restrict__ fcb,
                          float* __restrict__ out)
{
    const int gw   = (blockIdx.x * blockDim.x + threadIdx.x) >> 5;
    const int lane = threadIdx.x & 31;
    if (gw >= B) return;
    float sum = 0.f;
    #pragma unroll
    for (int qq = 0; qq < 4; qq++)
        sum += g_pooled[gw * 128 + qq * 32 + lane] * fcw[qq * 32 + lane];
    #pragma unroll
    for (int o = 16; o; o >>= 1) sum += __shfl_xor_sync(0xffffffffu, sum, o);
    if (lane == 0) out[gw] = sum * (1.f / 512.f) + fcb[0];
}

// =======================================================================
extern "C" void kernel_launch(void* const* d_in, const int* in_sizes, int n_in,
                              void* d_out, int out_size)
{
    const float* x     = (const float*)d_in[0];
    const float* Wih0f = (const float*)d_in[1];
    const float* Whh0f = (const float*)d_in[2];
    const float* b0f   = (const float*)d_in[3];
    const float* Wih0b = (const float*)d_in[4];
    const float* Whh0b = (const float*)d_in[5];
    const float* b0b   = (const float*)d_in[6];
    const float* Wih1f = (const float*)d_in[7];
    const float* Whh1f = (const float*)d_in[8];
    const float* b1f   = (const float*)d_in[9];
    const float* Wih1b = (const float*)d_in[10];
    const float* Whh1b = (const float*)d_in[11];
    const float* b1b   = (const float*)d_in[12];
    const float* fcw   = (const float*)d_in[13];
    const float* fcb   = (const float*)d_in[14];

    prep_btd<<<128, 512>>>(Wih1f, Wih1b);
    lstm_l0<<<dim3(B / RC, 2), 256>>>(x, Wih0f, Whh0f, b0f, Wih0b, Whh0b, b0b);
    cudaFuncSetAttribute(gemm_xp1, cudaFuncAttributeMaxDynamicSharedMemorySize, SMEM_GEMM);
    gemm_xp1<<<dim3(2048, 4), 256, SMEM_GEMM>>>(b1f, b1b);
    lstm_l1<<<dim3(B / RC, 2), 256>>>(Whh1f, Whh1b);
    fc_kernel<<<32, 512>>>(fcw, fcb, (float*)d_out);
}

// round 5
// speedup vs baseline: 1.7663x; 1.7017x over previous
#include <cuda_runtime.h>

typedef unsigned long long ULL;

// ---------- packed fp32x2 helpers ----------
__device__ __forceinline__ void ffma2(ULL &d, ULL a, ULL b) {
    asm("fma.rn.f32x2 %0, %1, %2, %0;" : "+l"(d) : "l"(a), "l"(b));
}
__device__ __forceinline__ float2 unpack2(ULL v) {
    float2 f; asm("mov.b64 {%0,%1}, %2;" : "=f"(f.x), "=f"(f.y) : "l"(v)); return f;
}
__device__ __forceinline__ ULL pack2(float lo, float hi) {
    ULL r; asm("mov.b64 %0, {%1,%2};" : "=l"(r) : "f"(lo), "f"(hi)); return r;
}
__device__ __forceinline__ ULL dup2(float a) {
    ULL r; asm("mov.b64 %0, {%1,%1};" : "=l"(r) : "f"(a)); return r;
}

// ---------- activations: single-MUFU tanh (sm_90+ tanh.approx) ----------
__device__ __forceinline__ float tanh_ap(float x) {
    float r; asm("tanh.approx.f32 %0, %1;" : "=f"(r) : "f"(x)); return r;
}
__device__ __forceinline__ float sig_ap(float x) {
    return fmaf(0.5f, tanh_ap(0.5f * x), 0.5f);
}

// ---------- constants ----------
constexpr int B = 512, T = 512;
constexpr long BT = (long)B * T;
constexpr int RC = 4;

// ---------- scratch ----------
__device__ __align__(16) float g_h0T[128 * BT];   // layer-0 out, feature-major [k][b*T+t]
__device__ __align__(16) float g_xp1[BT * 512];   // layer-1 preacts [b*T+t][n]
__device__ __align__(16) ULL   g_Btd[128 * 512];  // Wih_l1^T, values duplicated (b,b)
__device__ float g_pooled[B * 128];

// =======================================================================
// Layer-0 biLSTM. grid (128, 2), block 256, 2 CTAs/SM.
// Thread owns gate row g*64+u (weights in 32 ULL regs), computes it for 4
// batch rows; broadcast LDS of h; 4-shfl gate exchange; MUFU.TANH acts.
// h0 written TRANSPOSED via 32-step smem history tiles (coalesced flush).
// =======================================================================
__global__ __launch_bounds__(256, 2) void lstm_l0(
    const float* __restrict__ x,
    const float* __restrict__ Wih_f, const float* __restrict__ Whh_f, const float* __restrict__ b_f,
    const float* __restrict__ Wih_b, const float* __restrict__ Whh_b, const float* __restrict__ b_b)
{
    const int dir = blockIdx.y;
    const int b0  = blockIdx.x * RC;
    const int tid = threadIdx.x;
    const int u   = tid >> 2;
    const int g   = tid & 3;
    const int row = g * 64 + u;

    const float* Wih = dir ? Wih_b : Wih_f;
    const float* Whh = dir ? Whh_b : Whh_f;
    const float* bb  = dir ? b_b   : b_f;

    __shared__ __align__(16) float h_s[2][RC * 64];
    __shared__ __align__(16) float4 x_s[2][RC];
    __shared__ __align__(16) float hist[RC][64][36];

    ULL w2[32];
    {
        const ULL* wp = (const ULL*)(Whh + row * 64);
        #pragma unroll
        for (int i = 0; i < 32; i++) w2[i] = wp[i];
    }
    const float4 wih = *(const float4*)(Wih + row * 4);
    const float bias = bb[row];

    const int lane = tid & 31;
    const int qb   = lane & ~3;

    for (int i = tid; i < RC * 64; i += 256) h_s[0][i] = 0.f;
    if (tid < RC) {
        const int t0 = dir ? (T - 1) : 0;
        x_s[0][tid] = *(const float4*)(x + ((long)(b0 + tid) * T + t0) * 4);
    }
    __syncthreads();

    float c[RC] = {0.f, 0.f, 0.f, 0.f};
    int p = 0;

    for (int s = 0; s < T; s++) {
        const int t = dir ? (T - 1 - s) : s;
        if (tid < RC) {
            const int sn = (s + 1 < T) ? s + 1 : s;
            const int tn = dir ? (T - 1 - sn) : sn;
            x_s[p ^ 1][tid] = *(const float4*)(x + ((long)(b0 + tid) * T + tn) * 4);
        }

        float pre[RC];
        #pragma unroll
        for (int j = 0; j < RC; j++) {
            ULL a0 = 0, a1 = 0;
            const ulonglong2* h4 = (const ulonglong2*)(h_s[p] + j * 64);
            #pragma unroll
            for (int k = 0; k < 16; k++) {
                ulonglong2 hv = h4[k];
                ffma2(a0, w2[2 * k],     hv.x);
                ffma2(a1, w2[2 * k + 1], hv.y);
            }
            const float2 f0 = unpack2(a0), f1 = unpack2(a1);
            const float4 xv = x_s[p][j];
            pre[j] = f0.x + f0.y + f1.x + f1.y + bias
                   + wih.x * xv.x + wih.y * xv.y + wih.z * xv.z + wih.w * xv.w;
        }

        #pragma unroll
        for (int j = 0; j < RC; j++) {
            const float act = (g == 2) ? tanh_ap(pre[j]) : sig_ap(pre[j]);
            const float iv = __shfl_sync(0xffffffffu, act, qb + 0);
            const float fv = __shfl_sync(0xffffffffu, act, qb + 1);
            const float gv = __shfl_sync(0xffffffffu, act, qb + 2);
            const float ov = __shfl_sync(0xffffffffu, act, qb + 3);
            c[j] = fmaf(fv, c[j], iv * gv);
            const float h = ov * tanh_ap(c[j]);
            if (g == 0) {
                h_s[p ^ 1][j * 64 + u] = h;
                hist[j][u][t & 31] = h;
            }
        }
        p ^= 1;
        __syncthreads();

        if ((s & 31) == 31) {
            const int tbase = t & ~31;
            #pragma unroll
            for (int w = 0; w < 8; w++) {
                const int e   = tid + w * 256;
                const int tw4 = e & 7;
                const int ju  = e >> 3;
                const int j   = ju >> 6, uu = ju & 63;
                const float4 v = *(const float4*)(&hist[j][uu][tw4 * 4]);
                *(float4*)(g_h0T + (long)(dir * 64 + uu) * BT + (long)(b0 + j) * T + tbase + tw4 * 4) = v;
            }
            __syncthreads();
        }
    }
}

// =======================================================================
// Prep: g_Btd[k][n] = dup2(Wih_l1[n][k])  (n = dir*256 + gate_row)
// =======================================================================
__global__ void prep_btd(const float* __restrict__ Wf, const float* __restrict__ Wb)
{
    const int idx = blockIdx.x * 512 + threadIdx.x;   // 65536
    const int k = idx >> 9, n = idx & 511;
    const float* W = (n & 256) ? Wb : Wf;
    g_Btd[idx] = dup2(W[(n & 255) * 128 + k]);
}

// =======================================================================
// xp1 GEMM: [BT x 512] = h0T^T [BT x 128] @ W^T + bias.
// 128m x 128n tile, K split 2x64 (97KB smem -> 2 CTAs/SM).
// A k-major straight copy; B pre-dup'd. CONFLICT-FREE fragment mapping:
// thread's n-pairs at jj*32 + tx*2  ->  B reads are contiguous-16B LDS.128.
// grid (2048, 4), block 256.
// =======================================================================
constexpr int AP = 132;
constexpr int SMEM_GEMM = 64 * AP * 4 + 64 * 128 * 8;   // 99328 B

__global__ __launch_bounds__(256, 2) void gemm_xp1(
    const float* __restrict__ bias_f, const float* __restrict__ bias_b)
{
    extern __shared__ char smraw[];
    float* As  = (float*)smraw;                  // [64][AP]   k-major, m fastest
    ULL*   Bsd = (ULL*)(smraw + 64 * AP * 4);    // [64][128]  dup'd pairs
    const int tid = threadIdx.x;
    const long m0 = (long)blockIdx.x * 128;
    const int  n0 = blockIdx.y * 128;

    const int tx = tid & 15;        // n-pair selector
    const int ty = tid >> 4;        // m-octet

    // acc[i][jj*2+h]: m-pair i (rows ty*8+2i, +1), n = n0 + jj*32 + tx*2 + h
    ULL acc[4][8];
    #pragma unroll
    for (int i = 0; i < 4; i++)
        #pragma unroll
        for (int j = 0; j < 8; j++) acc[i][j] = 0;

    for (int kc = 0; kc < 2; kc++) {
        const int k0 = kc * 64;
        __syncthreads();
        // A slab: straight coalesced copy (already k-major)
        #pragma unroll
        for (int i = 0; i < 8; i++) {
            const int e = tid + i * 256;
            const int k = e >> 5, m4 = (e & 31) * 4;
            *(float4*)(As + k * AP + m4) = *(const float4*)(g_h0T + (long)(k0 + k) * BT + m0 + m4);
        }
        // B slab: 64 k-rows x 128 ULL
        #pragma unroll
        for (int i = 0; i < 8; i++) {
            const int e = tid + i * 256;
            const int k = e >> 5, w = e & 31;
            *(ulonglong2*)(Bsd + k * 128 + w * 2) =
                *(const ulonglong2*)(g_Btd + (long)(k0 + k) * 512 + n0 + w * 2);
        }
        #pragma unroll
        for (int i = 0; i < 8; i++) {
            const int e = tid + i * 256;
            const int k = e >> 5, w = e & 31;
            *(ulonglong2*)(Bsd + k * 128 + 64 + w * 2) =
                *(const ulonglong2*)(g_Btd + (long)(k0 + k) * 512 + n0 + 64 + w * 2);
        }
        __syncthreads();

        #pragma unroll 4
        for (int k = 0; k < 64; k++) {
            const ulonglong2* ap = (const ulonglong2*)(As + k * AP + ty * 8);
            const ulonglong2 aA = ap[0], aB = ap[1];            // 4 m-pairs
            const ULL* brow = Bsd + k * 128 + tx * 2;
            const ulonglong2 b0p = *(const ulonglong2*)(brow);        // n = tx*2, +1
            const ulonglong2 b1p = *(const ulonglong2*)(brow + 32);   // n = 32+tx*2, +1
            const ulonglong2 b2p = *(const ulonglong2*)(brow + 64);
            const ulonglong2 b3p = *(const ulonglong2*)(brow + 96);
            ffma2(acc[0][0], aA.x, b0p.x); ffma2(acc[1][0], aA.y, b0p.x);
            ffma2(acc[2][0], aB.x, b0p.x); ffma2(acc[3][0], aB.y, b0p.x);
            ffma2(acc[0][1], aA.x, b0p.y); ffma2(acc[1][1], aA.y, b0p.y);
            ffma2(acc[2][1], aB.x, b0p.y); ffma2(acc[3][1], aB.y, b0p.y);
            ffma2(acc[0][2], aA.x, b1p.x); ffma2(acc[1][2], aA.y, b1p.x);
            ffma2(acc[2][2], aB.x, b1p.x); ffma2(acc[3][2], aB.y, b1p.x);
            ffma2(acc[0][3], aA.x, b1p.y); ffma2(acc[1][3], aA.y, b1p.y);
            ffma2(acc[2][3], aB.x, b1p.y); ffma2(acc[3][3], aB.y, b1p.y);
            ffma2(acc[0][4], aA.x, b2p.x); ffma2(acc[1][4], aA.y, b2p.x);
            ffma2(acc[2][4], aB.x, b2p.x); ffma2(acc[3][4], aB.y, b2p.x);
            ffma2(acc[0][5], aA.x, b2p.y); ffma2(acc[1][5], aA.y, b2p.y);
            ffma2(acc[2][5], aB.x, b2p.y); ffma2(acc[3][5], aB.y, b2p.y);
            ffma2(acc[0][6], aA.x, b3p.x); ffma2(acc[1][6], aA.y, b3p.x);
            ffma2(acc[2][6], aB.x, b3p.x); ffma2(acc[3][6], aB.y, b3p.x);
            ffma2(acc[0][7], aA.x, b3p.y); ffma2(acc[1][7], aA.y, b3p.y);
            ffma2(acc[2][7], aB.x, b3p.y); ffma2(acc[3][7], aB.y, b3p.y);
        }
    }

    // epilogue: +bias, store ULL pairs (n, n+1) per row; stride-8B coalesced
    const float* bp = (n0 & 256) ? bias_b : bias_f;
    float bj[8];
    #pragma unroll
    for (int jj = 0; jj < 4; jj++) {
        bj[jj * 2 + 0] = bp[((n0 & 255) + jj * 32 + tx * 2 + 0) & 255];
        bj[jj * 2 + 1] = bp[((n0 & 255) + jj * 32 + tx * 2 + 1) & 255];
    }
    #pragma unroll
    for (int i = 0; i < 4; i++) {
        const long m = m0 + ty * 8 + i * 2;
        float* r0 = g_xp1 + m * 512;
        float* r1 = r0 + 512;
        #pragma unroll
        for (int jj = 0; jj < 4; jj++) {
            const int n = n0 + jj * 32 + tx * 2;
            const float2 v0 = unpack2(acc[i][jj * 2 + 0]);   // n
            const float2 v1 = unpack2(acc[i][jj * 2 + 1]);   // n+1
            *(ULL*)(r0 + n) = pack2(v0.x + bj[jj * 2], v1.x + bj[jj * 2 + 1]);
            *(ULL*)(r1 + n) = pack2(v0.y + bj[jj * 2], v1.y + bj[jj * 2 + 1]);
        }
    }
}

// =======================================================================
// Layer-1 biLSTM (R2 structure + MUFU.TANH activations).
// =======================================================================
__global__ __launch_bounds__(256, 2) void lstm_l1(
    const float* __restrict__ Whh_f, const float* __restrict__ Whh_b)
{
    const int dir = blockIdx.y;
    const int b0  = blockIdx.x * RC;
    const int tid = threadIdx.x;
    const int u   = tid >> 2;
    const int g   = tid & 3;
    const int row = g * 64 + u;
    const float* Whh = dir ? Whh_b : Whh_f;

    __shared__ __align__(16) float h_s[2][RC * 64];

    ULL w2[32];
    {
        const ULL* wp = (const ULL*)(Whh + row * 64);
        #pragma unroll
        for (int i = 0; i < 32; i++) w2[i] = wp[i];
    }
    const int lane = tid & 31;
    const int qb   = lane & ~3;
    const int col  = dir * 256 + row;

    const float* xp_base[RC];
    #pragma unroll
    for (int j = 0; j < RC; j++)
        xp_base[j] = g_xp1 + (long)(b0 + j) * T * 512 + col;

    for (int i = tid; i < RC * 64; i += 256) h_s[0][i] = 0.f;

    float c[RC]    = {0.f, 0.f, 0.f, 0.f};
    float hsum[RC] = {0.f, 0.f, 0.f, 0.f};
    float xp_cur[RC];
    {
        const int t0 = dir ? (T - 1) : 0;
        #pragma unroll
        for (int j = 0; j < RC; j++) xp_cur[j] = __ldg(xp_base[j] + (long)t0 * 512);
    }
    __syncthreads();

    int p = 0;
    for (int s = 0; s < T; s++) {
        const int sn = (s + 1 < T) ? s + 1 : s;
        const int tn = dir ? (T - 1 - sn) : sn;
        float xp_nxt[RC];
        #pragma unroll
        for (int j = 0; j < RC; j++) xp_nxt[j] = __ldg(xp_base[j] + (long)tn * 512);

        float pre[RC];
        #pragma unroll
        for (int j = 0; j < RC; j++) {
            ULL a0 = 0, a1 = 0;
            const ulonglong2* h4 = (const ulonglong2*)(h_s[p] + j * 64);
            #pragma unroll
            for (int k = 0; k < 16; k++) {
                ulonglong2 hv = h4[k];
                ffma2(a0, w2[2 * k],     hv.x);
                ffma2(a1, w2[2 * k + 1], hv.y);
            }
            const float2 f0 = unpack2(a0), f1 = unpack2(a1);
            pre[j] = f0.x + f0.y + f1.x + f1.y + xp_cur[j];
        }

        #pragma unroll
        for (int j = 0; j < RC; j++) {
            const float act = (g == 2) ? tanh_ap(pre[j]) : sig_ap(pre[j]);
            const float iv = __shfl_sync(0xffffffffu, act, qb + 0);
            const float fv = __shfl_sync(0xffffffffu, act, qb + 1);
            const float gv = __shfl_sync(0xffffffffu, act, qb + 2);
            const float ov = __shfl_sync(0xffffffffu, act, qb + 3);
            c[j] = fmaf(fv, c[j], iv * gv);
            const float h = ov * tanh_ap(c[j]);
            hsum[j] += h;
            if (g == 0) h_s[p ^ 1][j * 64 + u] = h;
        }
        #pragma unroll
        for (int j = 0; j < RC; j++) xp_cur[j] = xp_nxt[j];
        p ^= 1;
        __syncthreads();
    }

    if (g == 0) {
        #pragma unroll
        for (int j = 0; j < RC; j++)
            g_pooled[(b0 + j) * 128 + dir * 64 + u] = hsum[j];
    }
}

// =======================================================================
__global__ void fc_kernel(const float* __restrict__ fcw, const float* __restrict__ fcb,
                          float* __restrict__ out)
{
    const int gw   = (blockIdx.x * blockDim.x + threadIdx.x) >> 5;
    const int lane = threadIdx.x & 31;
    if (gw >= B) return;
    float sum = 0.f;
    #pragma unroll
    for (int qq = 0; qq < 4; qq++)
        sum += g_pooled[gw * 128 + qq * 32 + lane] * fcw[qq * 32 + lane];
    #pragma unroll
    for (int o = 16; o; o >>= 1) sum += __shfl_xor_sync(0xffffffffu, sum, o);
    if (lane == 0) out[gw] = sum * (1.f / 512.f) + fcb[0];
}

// =======================================================================
extern "C" void kernel_launch(void* const* d_in, const int* in_sizes, int n_in,
                              void* d_out, int out_size)
{
    const float* x     = (const float*)d_in[0];
    const float* Wih0f = (const float*)d_in[1];
    const float* Whh0f = (const float*)d_in[2];
    const float* b0f   = (const float*)d_in[3];
    const float* Wih0b = (const float*)d_in[4];
    const float* Whh0b = (const float*)d_in[5];
    const float* b0b   = (const float*)d_in[6];
    const float* Wih1f = (const float*)d_in[7];
    const float* Whh1f = (const float*)d_in[8];
    const float* b1f   = (const float*)d_in[9];
    const float* Wih1b = (const float*)d_in[10];
    const float* Whh1b = (const float*)d_in[11];
    const float* b1b   = (const float*)d_in[12];
    const float* fcw   = (const float*)d_in[13];
    const float* fcb   = (const float*)d_in[14];

    prep_btd<<<128, 512>>>(Wih1f, Wih1b);
    lstm_l0<<<dim3(B / RC, 2), 256>>>(x, Wih0f, Whh0f, b0f, Wih0b, Whh0b, b0b);
    cudaFuncSetAttribute(gemm_xp1, cudaFuncAttributeMaxDynamicSharedMemorySize, SMEM_GEMM);
    gemm_xp1<<<dim3(2048, 4), 256, SMEM_GEMM>>>(b1f, b1b);
    lstm_l1<<<dim3(B / RC, 2), 256>>>(Whh1f, Whh1b);
    fc_kernel<<<32, 512>>>(fcw, fcb, (float*)d_out);
}